// round 15
// baseline (speedup 1.0000x reference)
#include <cuda_runtime.h>
#include <math.h>
#include <stdint.h>

#define BB   512
#define SS   512
#define HH   128
#define M_ROWS (BB*SS)          // 262144
#define G4   (4*HH)             // 512

// output layout (fp32: action, log_prob, value, h, c)
#define OFF_LP ((size_t)M_ROWS*9)
#define OFF_V  (OFF_LP + (size_t)M_ROWS)
#define OFF_H  (OFF_V + (size_t)M_ROWS)
#define OFF_C  (OFF_H + (size_t)2*BB*HH)

// pre-split weight buffer offsets (uint2 {tf32_hi, tf32_lo} per element)
#define WP_ENC1 0                          // 128x64
#define WP_ENC2 (WP_ENC1 + 128*64)         // 128x128
#define WP_WIH0 (WP_ENC2 + 128*128)        // 512x128
#define WP_WIH1 (WP_WIH0 + 512*128)        // 512x128
#define WP_CAT  (WP_WIH1 + 512*128)        // 128x128
#define WP_TOT  (WP_CAT  + 128*128)

// static scratch
__device__ float  g_A [(size_t)M_ROWS * G4];
__device__ float  g_Bf[(size_t)M_ROWS * HH];
__device__ float  g_Cf[(size_t)M_ROWS * HH];
__device__ float4 g_wq[2][32*512];
__device__ uint2  g_Wp[WP_TOT];
__device__ float  g_bcat[128];

typedef unsigned long long u64;

__device__ __forceinline__ uint32_t to_tf32(float x) {
    uint32_t u; asm("cvt.rna.tf32.f32 %0, %1;" : "=r"(u) : "f"(x)); return u;
}
__device__ __forceinline__ uint2 split_tf32(float x) {
    uint32_t h = to_tf32(x);
    uint32_t l = to_tf32(x - __uint_as_float(h));
    return make_uint2(h, l);
}
__device__ __forceinline__ void mma_tf32(float c[4], const uint32_t a[4],
                                         const uint32_t b[2]) {
    asm volatile(
        "mma.sync.aligned.m16n8k8.row.col.f32.tf32.tf32.f32 "
        "{%0,%1,%2,%3}, {%4,%5,%6,%7}, {%8,%9}, {%0,%1,%2,%3};"
        : "+f"(c[0]), "+f"(c[1]), "+f"(c[2]), "+f"(c[3])
        : "r"(a[0]), "r"(a[1]), "r"(a[2]), "r"(a[3]), "r"(b[0]), "r"(b[1]));
}
__device__ __forceinline__ u64 pk2(float lo, float hi) {
    u64 r; asm("mov.b64 %0, {%1, %2};" : "=l"(r) : "f"(lo), "f"(hi)); return r;
}
__device__ __forceinline__ void upk2(u64 v, float& lo, float& hi) {
    asm("mov.b64 {%0, %1}, %2;" : "=f"(lo), "=f"(hi) : "l"(v));
}
__device__ __forceinline__ void fma2(u64& acc, u64 a, u64 b) {
    asm("fma.rn.f32x2 %0, %1, %2, %0;" : "+l"(acc) : "l"(a), "l"(b));
}
__device__ __forceinline__ float sigf(float x) { return 1.0f / (1.0f + expf(-x)); }

// ---------------------------------------------------------------------------
// Compensated tf32 GEMM: C[M,N] = act(X@W^T + b1 (+b2)), ~fp32 precision.
// BM=128, BN=64, whole K in smem as {hi,lo} pairs. 256 thr, warp tile 32x32.
// ---------------------------------------------------------------------------
__global__ __launch_bounds__(256) void gemm_tf32c(
    const float* __restrict__ X, const uint2* __restrict__ Wp,
    const float* __restrict__ b1, const float* __restrict__ b2,
    float* __restrict__ C, int M, int N, int K, int relu)
{
    extern __shared__ uint2 sm2[];
    const int LD = K + 4;
    uint2* Xs = sm2;                // 128 x LD
    uint2* Ws = sm2 + 128 * LD;     // 64 x LD

    const int t  = threadIdx.x;
    const int bm = blockIdx.y * 128;
    const int bn = blockIdx.x * 64;
    const int K4 = K >> 2, K2 = K >> 1;

    for (int idx = t; idx < 128 * K4; idx += 256) {
        int row = idx / K4, c4 = idx % K4;
        float4 v = *(const float4*)(X + (size_t)(bm + row) * K + c4 * 4);
        uint2 e0 = split_tf32(v.x), e1 = split_tf32(v.y);
        uint2 e2 = split_tf32(v.z), e3 = split_tf32(v.w);
        uint4* dst = (uint4*)(Xs + row * LD + c4 * 4);
        dst[0] = make_uint4(e0.x, e0.y, e1.x, e1.y);
        dst[1] = make_uint4(e2.x, e2.y, e3.x, e3.y);
    }
    for (int idx = t; idx < 64 * K2; idx += 256) {
        int row = idx / K2, c = idx % K2;
        ((uint4*)(Ws + row * LD))[c] =
            ((const uint4*)(Wp + (size_t)(bn + row) * K))[c];
    }
    __syncthreads();

    const int warp = t >> 5, lane = t & 31;
    const int g = lane >> 2, tg = lane & 3;
    const int wm = (warp & 3) * 32;     // 4 m-warps
    const int wn = (warp >> 2) * 32;    // 2 n-warps

    float acc[2][4][4];
#pragma unroll
    for (int mf = 0; mf < 2; mf++)
#pragma unroll
        for (int nf = 0; nf < 4; nf++)
#pragma unroll
            for (int q = 0; q < 4; q++) acc[mf][nf][q] = 0.f;

    for (int ks = 0; ks < K; ks += 8) {
        uint32_t ah[2][4], al[2][4];
#pragma unroll
        for (int mf = 0; mf < 2; mf++) {
            int r0 = wm + mf * 16;
            uint2 e;
            e = Xs[(r0 + g)     * LD + ks + tg];     ah[mf][0] = e.x; al[mf][0] = e.y;
            e = Xs[(r0 + g + 8) * LD + ks + tg];     ah[mf][1] = e.x; al[mf][1] = e.y;
            e = Xs[(r0 + g)     * LD + ks + tg + 4]; ah[mf][2] = e.x; al[mf][2] = e.y;
            e = Xs[(r0 + g + 8) * LD + ks + tg + 4]; ah[mf][3] = e.x; al[mf][3] = e.y;
        }
        uint32_t bh[4][2], bl[4][2];
#pragma unroll
        for (int nf = 0; nf < 4; nf++) {
            int n0 = wn + nf * 8;
            uint2 e;
            e = Ws[(n0 + g) * LD + ks + tg];     bh[nf][0] = e.x; bl[nf][0] = e.y;
            e = Ws[(n0 + g) * LD + ks + tg + 4]; bh[nf][1] = e.x; bl[nf][1] = e.y;
        }
#pragma unroll
        for (int mf = 0; mf < 2; mf++)
#pragma unroll
            for (int nf = 0; nf < 4; nf++) {
                mma_tf32(acc[mf][nf], al[mf], bh[nf]);
                mma_tf32(acc[mf][nf], ah[mf], bl[nf]);
                mma_tf32(acc[mf][nf], ah[mf], bh[nf]);
            }
    }

#pragma unroll
    for (int mf = 0; mf < 2; mf++) {
#pragma unroll
        for (int nf = 0; nf < 4; nf++) {
            int row = bm + wm + mf * 16 + g;
            int col = bn + wn + nf * 8 + tg * 2;
            float bb0 = __ldg(&b1[col])     + (b2 ? __ldg(&b2[col])     : 0.f);
            float bb1 = __ldg(&b1[col + 1]) + (b2 ? __ldg(&b2[col + 1]) : 0.f);
            float2 v0, v1;
            v0.x = acc[mf][nf][0] + bb0; v0.y = acc[mf][nf][1] + bb1;
            v1.x = acc[mf][nf][2] + bb0; v1.y = acc[mf][nf][3] + bb1;
            if (relu) {
                v0.x = fmaxf(v0.x, 0.f); v0.y = fmaxf(v0.y, 0.f);
                v1.x = fmaxf(v1.x, 0.f); v1.y = fmaxf(v1.y, 0.f);
            }
            *(float2*)(C + (size_t)row * N + col)       = v0;
            *(float2*)(C + (size_t)(row + 8) * N + col) = v1;
        }
    }
}

// split a weight matrix into {tf32 hi, tf32 lo}
__global__ void split_w(const float* __restrict__ W, uint2* __restrict__ Wp, int n)
{
    int i = blockIdx.x * 256 + threadIdx.x;
    if (i < n) Wp[i] = split_tf32(__ldg(&W[i]));
}

// stack am_w1|cr_w1 -> split, plus bias concat
__global__ void pack_heads(const float* __restrict__ am_w1, const float* __restrict__ am_b1,
                           const float* __restrict__ cr_w1, const float* __restrict__ cr_b1,
                           uint2* __restrict__ Wp, float* __restrict__ bc)
{
    int i = blockIdx.x * 256 + threadIdx.x;      // 16384
    int n = i >> 7, k = i & 127;
    float w = (n < 64) ? __ldg(&am_w1[n * 128 + k]) : __ldg(&cr_w1[(n - 64) * 128 + k]);
    Wp[i] = split_tf32(w);
    if (i < 128) bc[i] = (i < 64) ? __ldg(&am_b1[i]) : __ldg(&cr_b1[i - 64]);
}

// LayerNorm(128)+ReLU, one warp per row
__global__ __launch_bounds__(256) void ln_relu_kernel(
    const float* __restrict__ in, float* __restrict__ out,
    const float* __restrict__ gw, const float* __restrict__ bw)
{
    int warp = threadIdx.x >> 5, lane = threadIdx.x & 31;
    size_t row = (size_t)blockIdx.x * 8 + warp;
    float4 v = ((const float4*)(in + row * 128))[lane];
    float s  = v.x + v.y + v.z + v.w;
    float sq = v.x*v.x + v.y*v.y + v.z*v.z + v.w*v.w;
#pragma unroll
    for (int o = 16; o > 0; o >>= 1) {
        s  += __shfl_xor_sync(0xffffffffu, s,  o);
        sq += __shfl_xor_sync(0xffffffffu, sq, o);
    }
    float mean = s * (1.f / 128.f);
    float var  = sq * (1.f / 128.f) - mean * mean;
    float rstd = rsqrtf(var + 1e-5f);
    float4 g4 = __ldg((const float4*)gw + lane);
    float4 b4 = __ldg((const float4*)bw + lane);
    float4 o4;
    o4.x = fmaxf((v.x - mean) * rstd * g4.x + b4.x, 0.f);
    o4.y = fmaxf((v.y - mean) * rstd * g4.y + b4.y, 0.f);
    o4.z = fmaxf((v.z - mean) * rstd * g4.z + b4.z, 0.f);
    o4.w = fmaxf((v.w - mean) * rstd * g4.w + b4.w, 0.f);
    ((float4*)(out + row * 128))[lane] = o4;
}

// pack whh(512x128): wq[k4*512+j] = whh[j][4k4..4k4+3]
__global__ void pack_whh(const float* __restrict__ whh, float4* __restrict__ wq)
{
    int idx = blockIdx.x * 256 + threadIdx.x;    // 16384
    int k4 = idx & 31, jj = idx >> 5;
    wq[k4 * 512 + jj] = *(const float4*)(whh + (size_t)jj * 128 + k4 * 4);
}

// ---------------------------------------------------------------------------
// Sequential masked LSTM pass. 128 CTAs x 512 thr, 4 batch rows/CTA.
// Inner dot via packed fma.rn.f32x2 (halves FMA-pipe issues).
// ---------------------------------------------------------------------------
#define SK4 24
#define PASS_SMEM (SK4*512*16 + 512*4 + 2048*4)   // 206848

__global__ __launch_bounds__(512, 1) void lstm_pass(
    const float* __restrict__ gi, const float* __restrict__ masks,
    const float4* __restrict__ wq, float* __restrict__ hout,
    float* __restrict__ hfin, float* __restrict__ cfin)
{
    extern __shared__ float sm[];
    float4* ws = (float4*)sm;              // SK4*512 float4
    float*  hs = sm + SK4 * 512 * 4;       // 512
    float*  gs = hs + 512;                 // 2048

    const int j  = threadIdx.x;
    const int b0 = blockIdx.x << 2;
    const int r  = j >> 7, u = j & 127;

#pragma unroll
    for (int k4 = 0; k4 < SK4; k4++) ws[k4 * 512 + j] = __ldg(wq + k4 * 512 + j);
    hs[j] = 0.f;
    float creg = 0.f;
    __syncthreads();

    const float* mrow  = masks + (size_t)(b0 + r) * SS;
    float*       hw    = hout + ((size_t)(b0 + r) * SS) * HH + u;
    const float* gbase = gi + ((size_t)b0 * SS) * G4 + j;
    const size_t gstr  = (size_t)SS * G4;
    const float4* hq   = (const float4*)hs;

    float p0 = __ldg(gbase);
    float p1 = __ldg(gbase + gstr);
    float p2 = __ldg(gbase + 2 * gstr);
    float p3 = __ldg(gbase + 3 * gstr);

    for (int t = 0; t < SS; t++) {
        float m = __ldg(mrow + t);
        hs[j] *= m;
        creg  *= m;
        __syncthreads();

        u64 A0 = pk2(p0, 0.f), B0 = 0ull;
        u64 A1 = pk2(p1, 0.f), B1 = 0ull;
        u64 A2 = pk2(p2, 0.f), B2 = 0ull;
        u64 A3 = pk2(p3, 0.f), B3 = 0ull;

        int tn = (t + 1 < SS) ? (t + 1) : t;
        const float* gb = gbase + (size_t)tn * G4;
        p0 = __ldg(gb);
        p1 = __ldg(gb + gstr);
        p2 = __ldg(gb + 2 * gstr);
        p3 = __ldg(gb + 3 * gstr);

#pragma unroll
        for (int k4 = 0; k4 < SK4; k4++) {
            float4 w  = ws[k4 * 512 + j];
            u64 wlo = pk2(w.x, w.y), whi = pk2(w.z, w.w);
            float4 h0 = hq[k4], h1 = hq[32 + k4], h2 = hq[64 + k4], h3 = hq[96 + k4];
            fma2(A0, wlo, pk2(h0.x, h0.y)); fma2(B0, whi, pk2(h0.z, h0.w));
            fma2(A1, wlo, pk2(h1.x, h1.y)); fma2(B1, whi, pk2(h1.z, h1.w));
            fma2(A2, wlo, pk2(h2.x, h2.y)); fma2(B2, whi, pk2(h2.z, h2.w));
            fma2(A3, wlo, pk2(h3.x, h3.y)); fma2(B3, whi, pk2(h3.z, h3.w));
        }
#pragma unroll
        for (int k4 = SK4; k4 < 32; k4++) {
            float4 w  = __ldg(wq + k4 * 512 + j);
            u64 wlo = pk2(w.x, w.y), whi = pk2(w.z, w.w);
            float4 h0 = hq[k4], h1 = hq[32 + k4], h2 = hq[64 + k4], h3 = hq[96 + k4];
            fma2(A0, wlo, pk2(h0.x, h0.y)); fma2(B0, whi, pk2(h0.z, h0.w));
            fma2(A1, wlo, pk2(h1.x, h1.y)); fma2(B1, whi, pk2(h1.z, h1.w));
            fma2(A2, wlo, pk2(h2.x, h2.y)); fma2(B2, whi, pk2(h2.z, h2.w));
            fma2(A3, wlo, pk2(h3.x, h3.y)); fma2(B3, whi, pk2(h3.z, h3.w));
        }
        float xlo, xhi, a0, a1, a2, a3;
        upk2(A0, xlo, xhi); a0 = xlo + xhi; upk2(B0, xlo, xhi); a0 += xlo + xhi;
        upk2(A1, xlo, xhi); a1 = xlo + xhi; upk2(B1, xlo, xhi); a1 += xlo + xhi;
        upk2(A2, xlo, xhi); a2 = xlo + xhi; upk2(B2, xlo, xhi); a2 += xlo + xhi;
        upk2(A3, xlo, xhi); a3 = xlo + xhi; upk2(B3, xlo, xhi); a3 += xlo + xhi;

        gs[j] = a0; gs[512 + j] = a1; gs[1024 + j] = a2; gs[1536 + j] = a3;
        __syncthreads();

        int gb2 = r * 512 + u;
        float xi = gs[gb2], xf = gs[gb2 + 128], xg = gs[gb2 + 256], xo = gs[gb2 + 384];
        float c = sigf(xf) * creg + sigf(xi) * tanhf(xg);
        float h = sigf(xo) * tanhf(c);
        creg = c;
        hs[j] = h;
        hw[(size_t)t * HH] = h;
    }
    hfin[(size_t)(b0 + r) * HH + u] = hs[j];
    cfin[(size_t)(b0 + r) * HH + u] = creg;
}

// heads epilogue: 1 thread per row; t12 = [row][actor 0:64 | critic 64:128]
__global__ __launch_bounds__(256) void heads_kernel(
    const float* __restrict__ t12, const float* __restrict__ noise,
    const float* __restrict__ am_w2, const float* __restrict__ am_b2,
    const float* __restrict__ log_std,
    const float* __restrict__ cr_w2, const float* __restrict__ cr_b2,
    float* __restrict__ out)
{
    __shared__ float w2s[9 * 64];
    __shared__ float cw[64];
    __shared__ float b2a[9], lsa[9], crb[1];
    int tid = threadIdx.x;
    for (int i = tid; i < 576; i += 256) w2s[i] = __ldg(&am_w2[i]);
    if (tid < 64) cw[tid] = __ldg(&cr_w2[tid]);
    if (tid < 9) {
        b2a[tid] = __ldg(&am_b2[tid]);
        lsa[tid] = fminf(fmaxf(__ldg(&log_std[tid]), -4.f), 0.f);
    }
    if (tid == 0) crb[0] = __ldg(&cr_b2[0]);
    __syncthreads();

    size_t row = (size_t)blockIdx.x * 256 + tid;
    const float4* p1 = (const float4*)(t12 + row * 128);
    const float4* p2 = (const float4*)(t12 + row * 128 + 64);
    float mean[9];
#pragma unroll
    for (int a = 0; a < 9; a++) mean[a] = b2a[a];
    float val = crb[0];
#pragma unroll 4
    for (int k4 = 0; k4 < 16; k4++) {
        float4 x1 = __ldg(p1 + k4);
        float4 x2 = __ldg(p2 + k4);
        int k = k4 * 4;
#pragma unroll
        for (int a = 0; a < 9; a++) {
            const float* wr = &w2s[a * 64 + k];
            mean[a] += x1.x * wr[0] + x1.y * wr[1] + x1.z * wr[2] + x1.w * wr[3];
        }
        val += x2.x * cw[k] + x2.y * cw[k+1] + x2.z * cw[k+2] + x2.w * cw[k+3];
    }
    float lp = 0.f;
#pragma unroll
    for (int a = 0; a < 9; a++) {
        float mm = tanhf(mean[a]);
        float ls = lsa[a];
        float sd = expf(ls);
        float nz = __ldg(noise + row * 9 + a);
        float act = mm + sd * nz;
        float z   = (act - mm) / sd;
        lp += -0.5f * z * z - ls;
        out[row * 9 + a] = act;
    }
    lp -= 9.f * 0.9189385332046727f;
    out[OFF_LP + row] = lp;
    out[OFF_V  + row] = val;
}

// ---------------------------------------------------------------------------
extern "C" void kernel_launch(void* const* d_in, const int* in_sizes, int n_in,
                              void* d_out, int out_size)
{
    (void)in_sizes; (void)n_in; (void)out_size;
    const float* obs    = (const float*)d_in[0];
    const float* masks  = (const float*)d_in[1];
    const float* noise  = (const float*)d_in[2];
    const float* enc_w1 = (const float*)d_in[3];
    const float* enc_b1 = (const float*)d_in[4];
    const float* ln_g   = (const float*)d_in[5];
    const float* ln_b   = (const float*)d_in[6];
    const float* enc_w2 = (const float*)d_in[7];
    const float* enc_b2 = (const float*)d_in[8];
    const float* wih0   = (const float*)d_in[9];
    const float* whh0   = (const float*)d_in[10];
    const float* bih0   = (const float*)d_in[11];
    const float* bhh0   = (const float*)d_in[12];
    const float* wih1   = (const float*)d_in[13];
    const float* whh1   = (const float*)d_in[14];
    const float* bih1   = (const float*)d_in[15];
    const float* bhh1   = (const float*)d_in[16];
    const float* am_w1  = (const float*)d_in[17];
    const float* am_b1  = (const float*)d_in[18];
    const float* am_w2  = (const float*)d_in[19];
    const float* am_b2  = (const float*)d_in[20];
    const float* log_std= (const float*)d_in[21];
    const float* cr_w1  = (const float*)d_in[22];
    const float* cr_b1  = (const float*)d_in[23];
    const float* cr_w2  = (const float*)d_in[24];
    const float* cr_b2  = (const float*)d_in[25];
    float* out = (float*)d_out;

    float *A, *Bf, *Cf, *bcat; float4 *wq; uint2 *Wp;
    cudaGetSymbolAddress((void**)&A,    g_A);
    cudaGetSymbolAddress((void**)&Bf,   g_Bf);
    cudaGetSymbolAddress((void**)&Cf,   g_Cf);
    cudaGetSymbolAddress((void**)&wq,   g_wq);
    cudaGetSymbolAddress((void**)&Wp,   g_Wp);
    cudaGetSymbolAddress((void**)&bcat, g_bcat);

    const int sm64  = 192 * 68  * 8;   // K=64  -> 104448
    const int sm128 = 192 * 132 * 8;   // K=128 -> 202752
    cudaFuncSetAttribute(lstm_pass,
        cudaFuncAttributeMaxDynamicSharedMemorySize, PASS_SMEM);
    cudaFuncSetAttribute(gemm_tf32c,
        cudaFuncAttributeMaxDynamicSharedMemorySize, sm128);

    // weight preprocessing
    pack_whh<<<64, 256>>>(whh0, wq);
    pack_whh<<<64, 256>>>(whh1, wq + 32 * 512);
    split_w<<<32, 256>>>(enc_w1, Wp + WP_ENC1, 128 * 64);
    split_w<<<64, 256>>>(enc_w2, Wp + WP_ENC2, 128 * 128);
    split_w<<<256, 256>>>(wih0,  Wp + WP_WIH0, 512 * 128);
    split_w<<<256, 256>>>(wih1,  Wp + WP_WIH1, 512 * 128);
    pack_heads<<<64, 256>>>(am_w1, am_b1, cr_w1, cr_b1, Wp + WP_CAT, bcat);

    dim3 g2(2, 2048), g8(8, 2048);
    // encoder
    gemm_tf32c<<<g2, 256, sm64 >>>(obs, Wp + WP_ENC1, enc_b1, nullptr, Bf,
                                   M_ROWS, 128, 64, 0);
    ln_relu_kernel<<<M_ROWS / 8, 256>>>(Bf, Cf, ln_g, ln_b);
    gemm_tf32c<<<g2, 256, sm128>>>(Cf, Wp + WP_ENC2, enc_b2, nullptr, Bf,
                                   M_ROWS, 128, 128, 1);
    // layer 0
    gemm_tf32c<<<g8, 256, sm128>>>(Bf, Wp + WP_WIH0, bih0, bhh0, A,
                                   M_ROWS, 512, 128, 0);
    lstm_pass<<<128, 512, PASS_SMEM>>>(A, masks, wq, Cf, out + OFF_H, out + OFF_C);
    // layer 1
    gemm_tf32c<<<g8, 256, sm128>>>(Cf, Wp + WP_WIH1, bih1, bhh1, A,
                                   M_ROWS, 512, 128, 0);
    lstm_pass<<<128, 512, PASS_SMEM>>>(A, masks, wq + 32 * 512, Bf,
                                       out + OFF_H + (size_t)BB * HH,
                                       out + OFF_C + (size_t)BB * HH);
    // fused heads hidden GEMM + epilogue
    gemm_tf32c<<<g2, 256, sm128>>>(Bf, Wp + WP_CAT, bcat, nullptr, Cf,
                                   M_ROWS, 128, 128, 1);
    heads_kernel<<<M_ROWS / 256, 256>>>(Cf, noise, am_w2, am_b2, log_std,
                                        cr_w2, cr_b2, out);
}